// round 1
// baseline (speedup 1.0000x reference)
#include <cuda_runtime.h>
#include <cuda_bf16.h>

// Problem constants
#define B_     8
#define H_     8
#define N1_    32
#define N2_    32
#define SLEN   1024          // N1*N2
#define HD     64            // head_dim = 512/8
#define NROWS  (B_*H_*SLEN)  // 65536 query rows

// Output layout: concatenation of flattened outputs in reference order
#define OFF_SINQ 0
#define CNT_SINQ (B_*H_*SLEN*HD)          // 4194304
#define OFF_COSQ (OFF_SINQ + CNT_SINQ)    // 4194304
#define OFF_SINK (OFF_COSQ + CNT_SINQ)    // 8388608
#define CNT_SINK (SLEN*HD)                // 65536
#define OFF_COSK (OFF_SINK + CNT_SINK)    // 8454144
#define OFF_MASK (OFF_COSK + CNT_SINK)    // 8519680

// ---------------------------------------------------------------------------
// Kernel 1: sin_k / cos_k.  phase_k[s][d] = (i+j) * angle[d], angle repeats
// pairwise so only 32 distinct values per row; each thread does one distinct
// phase and writes float2 pairs.
// ---------------------------------------------------------------------------
__global__ void k_sincos_k(const float* __restrict__ angle,
                           float* __restrict__ out)
{
    int tid = blockIdx.x * blockDim.x + threadIdx.x;   // 0 .. SLEN*32-1
    if (tid >= SLEN * (HD/2)) return;
    int s = tid >> 5;          // row
    int d = tid & 31;          // distinct-angle index
    int i = s >> 5;
    int j = s & 31;
    float phase = (float)(i + j) * angle[2*d];
    float sv, cv;
    sincosf(phase, &sv, &cv);
    float2* sink = (float2*)(out + OFF_SINK);
    float2* cosk = (float2*)(out + OFF_COSK);
    sink[s*(HD/2) + d] = make_float2(sv, sv);
    cosk[s*(HD/2) + d] = make_float2(cv, cv);
}

// ---------------------------------------------------------------------------
// Kernel 2: per query-row (b,h,s): fused sin_q/cos_q row + mask row.
// mask[ki,kj] = exp(L*|a-ki|) * exp(L*|c-kj|), normalized by rsqrt(s1*s2).
// Block = 256 threads: warp0 -> ek1 + sum, warp1 -> ek2 + sum,
// warp2 -> sincos row, then all threads write the 1024-float mask row.
// ---------------------------------------------------------------------------
__global__ __launch_bounds__(256, 8)
void k_row(const float* __restrict__ offsets,   // [B,H,N1,N2,2]
           const float* __restrict__ angle,     // [64]
           const float* __restrict__ decay,     // [8]
           float* __restrict__ out)
{
    const int row = blockIdx.x;           // 0 .. NROWS-1
    const int h   = (row >> 10) & (H_-1);
    const int s   = row & (SLEN-1);
    const int i   = s >> 5;
    const int j   = s & 31;

    __shared__ float ek1[N1_];
    __shared__ float ek2[N2_];
    __shared__ float sums[2];

    // offsets stored as pairs -> float2 indexed by row
    const float2 off = ((const float2*)offsets)[row];
    const float a = (float)i + off.x;
    const float c = (float)j + off.y;
    const float L = decay[h];

    const int tid  = threadIdx.x;
    const int warp = tid >> 5;
    const int lane = tid & 31;

    if (warp == 0) {
        float e = __expf(L * fabsf(a - (float)lane));
        ek1[lane] = e;
        // warp sum
        float ssum = e;
        #pragma unroll
        for (int o = 16; o > 0; o >>= 1)
            ssum += __shfl_xor_sync(0xFFFFFFFFu, ssum, o);
        if (lane == 0) sums[0] = ssum;
    } else if (warp == 1) {
        float e = __expf(L * fabsf(c - (float)lane));
        ek2[lane] = e;
        float ssum = e;
        #pragma unroll
        for (int o = 16; o > 0; o >>= 1)
            ssum += __shfl_xor_sync(0xFFFFFFFFu, ssum, o);
        if (lane == 0) sums[1] = ssum;
    } else if (warp == 2) {
        // sin_q / cos_q: 32 distinct phases (angle repeats pairwise)
        float phase = (a + c) * angle[2*lane];
        float sv, cv;
        sincosf(phase, &sv, &cv);
        float2* sinq = (float2*)(out + OFF_SINQ) + (size_t)row * (HD/2);
        float2* cosq = (float2*)(out + OFF_COSQ) + (size_t)row * (HD/2);
        sinq[lane] = make_float2(sv, sv);
        cosq[lane] = make_float2(cv, cv);
    }
    __syncthreads();

    const float r = rsqrtf(sums[0] * sums[1]);

    // 1024 mask values per row; 256 threads x 4 (float4)
    float4* mrow = (float4*)(out + OFF_MASK + (size_t)row * SLEN);
    const int idx = tid * 4;         // 0..1020, multiple of 4
    const int ki  = idx >> 5;
    const int kj  = idx & 31;
    const float p = r * ek1[ki];
    float4 v;
    v.x = p * ek2[kj + 0];
    v.y = p * ek2[kj + 1];
    v.z = p * ek2[kj + 2];
    v.w = p * ek2[kj + 3];
    mrow[tid] = v;
}

extern "C" void kernel_launch(void* const* d_in, const int* in_sizes, int n_in,
                              void* d_out, int out_size)
{
    // Defensive input identification by element count
    const float* offsets = nullptr;
    const float* angle   = nullptr;
    const float* decay   = nullptr;
    for (int k = 0; k < n_in; ++k) {
        if      (in_sizes[k] == B_*H_*N1_*N2_*2) offsets = (const float*)d_in[k];
        else if (in_sizes[k] == HD)              angle   = (const float*)d_in[k];
        else if (in_sizes[k] == H_)              decay   = (const float*)d_in[k];
    }
    float* out = (float*)d_out;

    k_sincos_k<<<(SLEN*(HD/2) + 255)/256, 256>>>(angle, out);
    k_row<<<NROWS, 256>>>(offsets, angle, decay, out);
}

// round 2
// speedup vs baseline: 1.5601x; 1.5601x over previous
#include <cuda_runtime.h>
#include <cuda_bf16.h>

// Problem constants
#define B_     8
#define H_     8
#define N1_    32
#define N2_    32
#define SLEN   1024          // N1*N2
#define HD     64            // head_dim = 512/8
#define NROWS  (B_*H_*SLEN)  // 65536 query rows

// Output layout: concatenation of flattened outputs in reference order
#define OFF_SINQ 0
#define CNT_SINQ (B_*H_*SLEN*HD)          // 4194304
#define OFF_COSQ (OFF_SINQ + CNT_SINQ)
#define OFF_SINK (OFF_COSQ + CNT_SINQ)    // 8388608
#define CNT_SINK (SLEN*HD)                // 65536
#define OFF_COSK (OFF_SINK + CNT_SINK)
#define OFF_MASK (OFF_COSK + CNT_SINK)    // 8519680

#define FULL 0xFFFFFFFFu

// ---------------------------------------------------------------------------
// One warp per query row. No smem, no block barriers.
//   lane l holds: e1 = exp(L*|a-l|), e2 = exp(L*|c-l|)
//   sums via butterfly shuffles; mask row = outer product via shuffles.
// Warps for rows < 1024 (b=0,h=0) additionally emit sin_k/cos_k for s=row.
// ---------------------------------------------------------------------------
__global__ __launch_bounds__(256, 8)
void k_row(const float* __restrict__ offsets,   // [B,H,N1,N2,2]
           const float* __restrict__ angle,     // [64]
           const float* __restrict__ decay,     // [8]
           float* __restrict__ out)
{
    const int warp_global = (blockIdx.x * blockDim.x + threadIdx.x) >> 5;
    const int lane        = threadIdx.x & 31;
    const int row         = warp_global;          // 0 .. NROWS-1
    const int h   = (row >> 10) & (H_-1);
    const int s   = row & (SLEN-1);
    const int i   = s >> 5;
    const int j   = s & 31;

    const float2 off = __ldg(((const float2*)offsets) + row);
    const float a = (float)i + off.x;
    const float c = (float)j + off.y;
    const float L = __ldg(decay + h);

    // per-lane exponentials
    const float fl = (float)lane;
    float e1 = __expf(L * fabsf(a - fl));
    float e2 = __expf(L * fabsf(c - fl));

    // warp sums of e1 and e2 (combined butterfly)
    float s1 = e1, s2 = e2;
    #pragma unroll
    for (int o = 16; o > 0; o >>= 1) {
        s1 += __shfl_xor_sync(FULL, s1, o);
        s2 += __shfl_xor_sync(FULL, s2, o);
    }
    const float r = rsqrtf(s1 * s2);

    // sin_q / cos_q : 32 distinct phases (angle repeats pairwise)
    {
        float phase = (a + c) * __ldg(angle + 2*lane);
        float sv, cv;
        sincosf(phase, &sv, &cv);
        float2* sinq = (float2*)(out + OFF_SINQ) + (size_t)row * (HD/2);
        float2* cosq = (float2*)(out + OFF_COSQ) + (size_t)row * (HD/2);
        sinq[lane] = make_float2(sv, sv);
        cosq[lane] = make_float2(cv, cv);
    }

    // sin_k / cos_k : rows 0..1023 (b=0,h=0) also emit key-side row s
    if (row < SLEN) {
        float phase = (float)(i + j) * __ldg(angle + 2*lane);
        float sv, cv;
        sincosf(phase, &sv, &cv);
        float2* sink = (float2*)(out + OFF_SINK) + (size_t)row * (HD/2);
        float2* cosk = (float2*)(out + OFF_COSK) + (size_t)row * (HD/2);
        sink[lane] = make_float2(sv, sv);
        cosk[lane] = make_float2(cv, cv);
    }

    // mask row: 1024 floats = 8 float4/lane, coalesced.
    // element idx of float4 (t,l) = (t*32+l)*4  ->  ki = t*4 + (l>>3), kj = (l&7)*4
    const int base2 = (lane & 7) * 4;
    const float q0 = __shfl_sync(FULL, e2, base2 + 0);
    const float q1 = __shfl_sync(FULL, e2, base2 + 1);
    const float q2 = __shfl_sync(FULL, e2, base2 + 2);
    const float q3 = __shfl_sync(FULL, e2, base2 + 3);

    float4* mrow = (float4*)(out + OFF_MASK + (size_t)row * SLEN);
    const int hi = lane >> 3;
    #pragma unroll
    for (int t = 0; t < 8; ++t) {
        const float p = r * __shfl_sync(FULL, e1, t*4 + hi);
        mrow[t*32 + lane] = make_float4(p*q0, p*q1, p*q2, p*q3);
    }
}

extern "C" void kernel_launch(void* const* d_in, const int* in_sizes, int n_in,
                              void* d_out, int out_size)
{
    const float* offsets = nullptr;
    const float* angle   = nullptr;
    const float* decay   = nullptr;
    for (int k = 0; k < n_in; ++k) {
        if      (in_sizes[k] == B_*H_*N1_*N2_*2) offsets = (const float*)d_in[k];
        else if (in_sizes[k] == HD)              angle   = (const float*)d_in[k];
        else if (in_sizes[k] == H_)              decay   = (const float*)d_in[k];
    }
    float* out = (float*)d_out;

    // one warp per row: 65536 warps = 8192 blocks of 256 threads
    k_row<<<NROWS/8, 256>>>(offsets, angle, decay, out);
}

// round 3
// speedup vs baseline: 1.6138x; 1.0344x over previous
#include <cuda_runtime.h>
#include <cuda_bf16.h>

// Problem constants
#define B_     8
#define H_     8
#define N1_    32
#define N2_    32
#define SLEN   1024          // N1*N2
#define HD     64            // head_dim = 512/8
#define NROWS  (B_*H_*SLEN)  // 65536 query rows

// Output layout: concatenation of flattened outputs in reference order
#define OFF_SINQ 0
#define CNT_SINQ (B_*H_*SLEN*HD)          // 4194304
#define OFF_COSQ (OFF_SINQ + CNT_SINQ)
#define OFF_SINK (OFF_COSQ + CNT_SINQ)    // 8388608
#define CNT_SINK (SLEN*HD)                // 65536
#define OFF_COSK (OFF_SINK + CNT_SINK)
#define OFF_MASK (OFF_COSK + CNT_SINK)    // 8519680

#define FULL 0xFFFFFFFFu

// ---------------------------------------------------------------------------
// One warp per query row. No smem, no block barriers. All stores streaming
// (.cs) — outputs are write-once, keep them out of L2's way.
// ---------------------------------------------------------------------------
__global__ __launch_bounds__(256, 8)
void k_row(const float* __restrict__ offsets,   // [B,H,N1,N2,2]
           const float* __restrict__ angle,     // [64]
           const float* __restrict__ decay,     // [8]
           float* __restrict__ out)
{
    const int warp_global = (blockIdx.x * blockDim.x + threadIdx.x) >> 5;
    const int lane        = threadIdx.x & 31;
    const int row         = warp_global;          // 0 .. NROWS-1
    const int h   = (row >> 10) & (H_-1);
    const int s   = row & (SLEN-1);
    const int i   = s >> 5;
    const int j   = s & 31;

    const float2 off = __ldg(((const float2*)offsets) + row);
    const float a = (float)i + off.x;
    const float c = (float)j + off.y;
    const float L = __ldg(decay + h);

    // per-lane exponentials
    const float fl = (float)lane;
    float e1 = __expf(L * fabsf(a - fl));
    float e2 = __expf(L * fabsf(c - fl));

    // warp sums of e1 and e2 (combined butterfly)
    float s1 = e1, s2 = e2;
    #pragma unroll
    for (int o = 16; o > 0; o >>= 1) {
        s1 += __shfl_xor_sync(FULL, s1, o);
        s2 += __shfl_xor_sync(FULL, s2, o);
    }
    const float r = rsqrtf(s1 * s2);

    // sin_q / cos_q : 32 distinct phases, pairwise-repeated -> 64 elements.
    // Lanes 0..15 each compute 2 adjacent distinct phases, store one float4.
    if (lane < HD/4) {
        const float sa = a + c;
        float p0 = sa * __ldg(angle + 4*lane);
        float p1 = sa * __ldg(angle + 4*lane + 2);
        float s0, c0, s1v, c1v;
        sincosf(p0, &s0, &c0);
        sincosf(p1, &s1v, &c1v);
        float4* sinq = (float4*)(out + OFF_SINQ) + (size_t)row * (HD/4);
        float4* cosq = (float4*)(out + OFF_COSQ) + (size_t)row * (HD/4);
        __stcs(sinq + lane, make_float4(s0, s0, s1v, s1v));
        __stcs(cosq + lane, make_float4(c0, c0, c1v, c1v));
    }

    // sin_k / cos_k : rows 0..1023 (b=0,h=0) also emit key-side row s
    if (row < SLEN && lane < HD/4) {
        const float sk = (float)(i + j);
        float p0 = sk * __ldg(angle + 4*lane);
        float p1 = sk * __ldg(angle + 4*lane + 2);
        float s0, c0, s1v, c1v;
        sincosf(p0, &s0, &c0);
        sincosf(p1, &s1v, &c1v);
        float4* sink = (float4*)(out + OFF_SINK) + (size_t)row * (HD/4);
        float4* cosk = (float4*)(out + OFF_COSK) + (size_t)row * (HD/4);
        __stcs(sink + lane, make_float4(s0, s0, s1v, s1v));
        __stcs(cosk + lane, make_float4(c0, c0, c1v, c1v));
    }

    // mask row: 1024 floats = 8 float4/lane, coalesced streaming stores.
    // element idx of float4 (t,l) = (t*32+l)*4 -> ki = t*4 + (l>>3), kj = (l&7)*4
    const int base2 = (lane & 7) * 4;
    const float q0 = __shfl_sync(FULL, e2, base2 + 0);
    const float q1 = __shfl_sync(FULL, e2, base2 + 1);
    const float q2 = __shfl_sync(FULL, e2, base2 + 2);
    const float q3 = __shfl_sync(FULL, e2, base2 + 3);

    float4* mrow = (float4*)(out + OFF_MASK + (size_t)row * SLEN);
    const int hi = lane >> 3;
    #pragma unroll
    for (int t = 0; t < 8; ++t) {
        const float p = r * __shfl_sync(FULL, e1, t*4 + hi);
        __stcs(mrow + t*32 + lane, make_float4(p*q0, p*q1, p*q2, p*q3));
    }
}

extern "C" void kernel_launch(void* const* d_in, const int* in_sizes, int n_in,
                              void* d_out, int out_size)
{
    const float* offsets = nullptr;
    const float* angle   = nullptr;
    const float* decay   = nullptr;
    for (int k = 0; k < n_in; ++k) {
        if      (in_sizes[k] == B_*H_*N1_*N2_*2) offsets = (const float*)d_in[k];
        else if (in_sizes[k] == HD)              angle   = (const float*)d_in[k];
        else if (in_sizes[k] == H_)              decay   = (const float*)d_in[k];
    }
    float* out = (float*)d_out;

    // one warp per row: 65536 warps = 8192 blocks of 256 threads
    k_row<<<NROWS/8, 256>>>(offsets, angle, decay, out);
}